// round 6
// baseline (speedup 1.0000x reference)
#include <cuda_runtime.h>
#include <cstddef>

// JPEG 8x8 blockify + orthonormal 2D DCT-II + QF quantization.
// image: [16,1,1024,1024] f32, qf: [16] f32 -> out [16,64,128,128] f32.
//
// R6: FOUR threads per 8x8 block (lane group q = lane&3). Each thread owns
// 2 columns (x[8][2] = 16 data regs). Column DCT thread-local; row DCT is a
// 3-stage shuffle butterfly across the 4-lane group (xor3, xor1, xor1) with
// per-lane coefficient float4s selected once from __constant__, so all lanes
// run the identical instruction stream. __launch_bounds__(256,6) -> <=42
// regs, 6 CTAs/SM (48 warps, 75% occupancy cap) to keep HBM fed.

#define A0 0.35355339059327373f  // 1/sqrt(8)
#define H1 0.49039264020161522f  // cos(1*pi/16)/2
#define H2 0.46193976625564337f  // cos(2*pi/16)/2
#define H3 0.41573480615127262f  // cos(3*pi/16)/2
#define H4 0.35355339059327376f  // cos(4*pi/16)/2
#define H5 0.27778511650980111f  // cos(5*pi/16)/2
#define H6 0.19134171618254489f  // cos(6*pi/16)/2
#define H7 0.09754516100806413f  // cos(7*pi/16)/2

__constant__ float c_qtab[64] = {
    16.f, 11.f, 10.f, 16.f, 24.f, 40.f, 51.f, 61.f,
    12.f, 12.f, 14.f, 19.f, 26.f, 58.f, 60.f, 55.f,
    14.f, 13.f, 16.f, 24.f, 40.f, 57.f, 69.f, 56.f,
    14.f, 17.f, 22.f, 29.f, 51.f, 87.f, 80.f, 62.f,
    18.f, 22.f, 37.f, 56.f, 68.f, 109.f, 103.f, 77.f,
    24.f, 36.f, 55.f, 64.f, 81.f, 104.f, 113.f, 92.f,
    49.f, 64.f, 78.f, 87.f, 103.f, 121.f, 120.f, 101.f,
    72.f, 92.f, 95.f, 98.f, 112.f, 100.f, 103.f, 99.f};

// Even-output coefficients for (A,B,C,D) per lane-q:
//  q0 -> l0 = A0*(ee0+ee1);  q1 -> l2 = H2*eo0+H6*eo1
//  q2 -> l4 = H4*(ee0-ee1);  q3 -> l6 = H6*eo0-H2*eo1
// with per-q meanings: q0:(A,B,C,D)=(ee0,ee1, eo0, eo1)
//                      q1:(ee1,ee0,-eo1,-eo0)
//                      q2:(ee0,ee1,-eo0,-eo1)
//                      q3:(ee1,ee0, eo1, eo0)
__constant__ float c_gev[16] = {
    A0,  A0,  0.f, 0.f,     // q0
    0.f, 0.f, -H6, -H2,     // q1
    H4, -H4,  0.f, 0.f,     // q2
    0.f, 0.f, -H2,  H6};    // q3

// Odd-output coefficients for (d0,d1,u0,u1) per lane-q:
//  q0:(o0,o1,o2,o3)->l1   q1:(o2,o3,o0,o1)->l3
//  q2:(-o3,-o2,-o1,-o0)->l5   q3:(-o1,-o0,-o3,-o2)->l7
__constant__ float c_god[16] = {
    H1,  H3,  H5,  H7,      // q0: l1
   -H1, -H5,  H3, -H7,      // q1: l3
   -H3, -H7,  H1, -H5,      // q2: l5
    H5, -H7,  H1, -H3};     // q3: l7

__device__ __forceinline__ void dct8(float& x0, float& x1, float& x2, float& x3,
                                     float& x4, float& x5, float& x6, float& x7) {
    float e0 = x0 + x7, e1 = x1 + x6, e2 = x2 + x5, e3 = x3 + x4;
    float o0 = x0 - x7, o1 = x1 - x6, o2 = x2 - x5, o3 = x3 - x4;
    float ee0 = e0 + e3, ee1 = e1 + e2;
    float eo0 = e0 - e3, eo1 = e1 - e2;
    x0 = A0 * (ee0 + ee1);
    x4 = H4 * (ee0 - ee1);
    x2 = H2 * eo0 + H6 * eo1;
    x6 = H6 * eo0 - H2 * eo1;
    x1 = H1 * o0 + H3 * o1 + H5 * o2 + H7 * o3;
    x3 = H3 * o0 - H7 * o1 - H1 * o2 - H5 * o3;
    x5 = H5 * o0 - H1 * o1 + H7 * o2 + H3 * o3;
    x7 = H7 * o0 - H5 * o1 + H3 * o2 - H1 * o3;
}

__global__ __launch_bounds__(256, 6) void jpeg_dct_kernel(
    const float* __restrict__ img,
    const float* __restrict__ qf,
    float* __restrict__ out) {
    __shared__ __align__(16) float sScale[64];

    int tid = blockIdx.x * 256 + threadIdx.x;
    int b = tid >> 16;  // 4 threads/block * 16384 blocks = 65536/image; CTA-uniform

    if (threadIdx.x < 64) {
        float q = qf[b];
        float factor = (q < 50.0f) ? (5000.0f / q) : (200.0f - 2.0f * q);
        sScale[threadIdx.x] = 100.0f / (c_qtab[threadIdx.x] * factor);
    }
    __syncthreads();

    int bid = tid >> 2;      // 8x8 block index
    int q = tid & 3;         // quarter: columns 2q, 2q+1
    int hb = (bid >> 7) & 127;
    int wb = bid & 127;

    // Loads: warp covers 256B contiguous per row. 8x LDG.64, front-batched.
    const float* p = img + ((size_t)b << 20) + (size_t)hb * 8192 + wb * 8 + q * 2;

    float x[8][2];
#pragma unroll
    for (int r = 0; r < 8; r++) {
        float2 v = *(const float2*)(p + (size_t)r * 1024);
        x[r][0] = v.x - 128.0f;
        x[r][1] = v.y - 128.0f;
    }

    // Column transform: thread-local, 2 columns.
    dct8(x[0][0], x[1][0], x[2][0], x[3][0], x[4][0], x[5][0], x[6][0], x[7][0]);
    dct8(x[0][1], x[1][1], x[2][1], x[3][1], x[4][1], x[5][1], x[6][1], x[7][1]);

    float4 ge = *(const float4*)&c_gev[q * 4];
    float4 go = *(const float4*)&c_god[q * 4];

    float* ob = out + ((size_t)b << 20) + (size_t)(q * 2) * 16384 + hb * 128 + wb;

#pragma unroll
    for (int k = 0; k < 8; k++) {
        float v0 = x[k][0], v1 = x[k][1];
        // Stage 1: pair lane q with lane 3-q (cols 6-2q, 7-2q)
        float p1 = __shfl_xor_sync(0xffffffffu, v1, 3);
        float p0 = __shfl_xor_sync(0xffffffffu, v0, 3);
        float s0 = v0 + p1, s1 = v1 + p0;   // e-values (order/sign per q)
        float d0 = v0 - p1, d1 = v1 - p0;   // o-values (order/sign per q)
        // Stage 2: exchange with lane q^1
        float t0 = __shfl_xor_sync(0xffffffffu, s0, 1);
        float t1 = __shfl_xor_sync(0xffffffffu, s1, 1);
        float u0 = __shfl_xor_sync(0xffffffffu, d0, 1);
        float u1 = __shfl_xor_sync(0xffffffffu, d1, 1);
        float A = s0 + t1, B = s1 + t0;
        float C = s0 - t1, D = s1 - t0;

        float ev = ge.x * A + ge.y * B + ge.z * C + ge.w * D;    // l = 2q
        float od = go.x * d0 + go.y * d1 + go.z * u0 + go.w * u1; // l = 2q+1

        float2 sc = *(const float2*)&sScale[k * 8 + q * 2];
        float* ok = ob + (size_t)(k * 8) * 16384;
        ok[0]     = ev * sc.x;
        ok[16384] = od * sc.y;
    }
}

extern "C" void kernel_launch(void* const* d_in, const int* in_sizes, int n_in,
                              void* d_out, int out_size) {
    const float* img = (const float*)d_in[0];
    const float* qf = (const float*)d_in[1];
    float* out = (float*)d_out;
    // 16 images * 16384 blocks * 4 threads = 1048576 threads -> 4096 CTAs
    jpeg_dct_kernel<<<4096, 256>>>(img, qf, out);
}